// round 1
// baseline (speedup 1.0000x reference)
#include <cuda_runtime.h>
#include <cstdint>

// Problem: sim[b,o] = sum_d |x[b,d] - c[o,d]|;  out = beta[o] * (max(sim)*1.001 - sim[b,o])
// Shapes (from reference): x[1024,512], centers[512,512], beta[512]. out fp32 [1024,512].

#define BM 32
#define BN 64
#define KC 16          // K elements per chunk
#define KP (KC / 2)    // K pairs per chunk
#define W_DIST 1.001f

__device__ int g_max_bits;   // bit-pattern of global max (sims are positive -> int order == float order)

__device__ __forceinline__ unsigned long long addx2(unsigned long long a, unsigned long long b) {
    unsigned long long r;
    asm("add.rn.f32x2 %0, %1, %2;" : "=l"(r) : "l"(a), "l"(b));
    return r;
}

__global__ void init_max_kernel() { g_max_bits = 0; }

__global__ __launch_bounds__(128) void sim_kernel(
    const float* __restrict__ x,       // [B, DIN]
    const float* __restrict__ c,       // [DOUT, DIN]
    float* __restrict__ out,           // [B, DOUT] (sim scratch)
    int DIN, int DOUT)
{
    // SMEM in k-pair-major layout: [pair][row] as float2 (two consecutive k-values)
    __shared__ float2 xs[KP][BM];      // 2 KB
    __shared__ float2 cs[KP][BN];      // 4 KB (stores NEGATED centers)
    __shared__ float wmax[4];

    const int tid = threadIdx.x;
    const int bm = blockIdx.y;
    const int bn = blockIdx.x;
    const int tr = tid >> 4;           // 0..7   -> m = tr + 8*i
    const int tc = tid & 15;           // 0..15  -> n = tc + 16*j

    unsigned long long acc[4][4];
#pragma unroll
    for (int i = 0; i < 4; i++)
#pragma unroll
        for (int j = 0; j < 4; j++) acc[i][j] = 0ULL;

    // ---- global-load mapping (coalesced float4) ----
    const int rl = tid >> 2;           // 0..31 : row within tile
    const int q  = tid & 3;            // 0..3  : float4-quad within K-chunk
    const float4* xg  = reinterpret_cast<const float4*>(x + (size_t)(bm * BM + rl) * DIN) + q;
    const float4* cg0 = reinterpret_cast<const float4*>(c + (size_t)(bn * BN + rl)      * DIN) + q;
    const float4* cg1 = reinterpret_cast<const float4*>(c + (size_t)(bn * BN + rl + 32) * DIN) + q;

    float4 vx  = *xg;
    float4 vc0 = *cg0;
    float4 vc1 = *cg1;

    const int nchunks = DIN / KC;
    for (int ch = 0; ch < nchunks; ch++) {
        __syncthreads();
        // store prefetched regs -> smem (centers negated so diff is a pure packed add)
        xs[q * 2 + 0][rl]      = make_float2(vx.x,  vx.y);
        xs[q * 2 + 1][rl]      = make_float2(vx.z,  vx.w);
        cs[q * 2 + 0][rl]      = make_float2(-vc0.x, -vc0.y);
        cs[q * 2 + 1][rl]      = make_float2(-vc0.z, -vc0.w);
        cs[q * 2 + 0][rl + 32] = make_float2(-vc1.x, -vc1.y);
        cs[q * 2 + 1][rl + 32] = make_float2(-vc1.z, -vc1.w);
        __syncthreads();

        // prefetch next chunk (LDG latency overlaps the compute below)
        if (ch + 1 < nchunks) {
            vx  = xg [(ch + 1) * (KC / 4)];
            vc0 = cg0[(ch + 1) * (KC / 4)];
            vc1 = cg1[(ch + 1) * (KC / 4)];
        }

#pragma unroll
        for (int p = 0; p < KP; p++) {
            unsigned long long a[4], b[4];
#pragma unroll
            for (int i = 0; i < 4; i++)
                a[i] = *reinterpret_cast<const unsigned long long*>(&xs[p][tr + 8 * i]);
#pragma unroll
            for (int j = 0; j < 4; j++)
                b[j] = *reinterpret_cast<const unsigned long long*>(&cs[p][tc + 16 * j]);
#pragma unroll
            for (int i = 0; i < 4; i++)
#pragma unroll
                for (int j = 0; j < 4; j++) {
                    unsigned long long d = addx2(a[i], b[j]);          // x - c (packed)
                    d &= 0x7FFFFFFF7FFFFFFFULL;                        // |.| on both halves (alu pipe)
                    acc[i][j] = addx2(acc[i][j], d);                   // packed accumulate
                }
        }
    }

    // ---- finalize: write sim, reduce max ----
    float tmax = 0.0f;
#pragma unroll
    for (int i = 0; i < 4; i++) {
        const int row = bm * BM + tr + 8 * i;
        float* orow = out + (size_t)row * DOUT + bn * BN;
#pragma unroll
        for (int j = 0; j < 4; j++) {
            float2 v = *reinterpret_cast<float2*>(&acc[i][j]);
            float s = v.x + v.y;
            orow[tc + 16 * j] = s;
            tmax = fmaxf(tmax, s);
        }
    }
#pragma unroll
    for (int off = 16; off > 0; off >>= 1)
        tmax = fmaxf(tmax, __shfl_xor_sync(0xffffffffu, tmax, off));
    if ((tid & 31) == 0) wmax[tid >> 5] = tmax;
    __syncthreads();
    if (tid == 0) {
        float m = fmaxf(fmaxf(wmax[0], wmax[1]), fmaxf(wmax[2], wmax[3]));
        atomicMax(&g_max_bits, __float_as_int(m));
    }
}

__global__ void epilogue_kernel(float* __restrict__ out,
                                const float* __restrict__ beta,
                                int dout_v4, int total_v4)
{
    const float gm = __int_as_float(g_max_bits) * W_DIST;
    int i = blockIdx.x * blockDim.x + threadIdx.x;
    if (i < total_v4) {
        float4 s = reinterpret_cast<float4*>(out)[i];
        float4 b = reinterpret_cast<const float4*>(beta)[i % dout_v4];
        float4 r;
        r.x = b.x * (gm - s.x);
        r.y = b.y * (gm - s.y);
        r.z = b.z * (gm - s.z);
        r.w = b.w * (gm - s.w);
        reinterpret_cast<float4*>(out)[i] = r;
    }
}

extern "C" void kernel_launch(void* const* d_in, const int* in_sizes, int n_in,
                              void* d_out, int out_size)
{
    const float* x    = (const float*)d_in[0];
    const float* c    = (const float*)d_in[1];
    const float* beta = (const float*)d_in[2];
    float* out = (float*)d_out;

    const int DOUT = in_sizes[2];
    const int DIN  = in_sizes[1] / DOUT;
    const int B    = in_sizes[0] / DIN;

    init_max_kernel<<<1, 1>>>();

    dim3 grid(DOUT / BN, B / BM);
    sim_kernel<<<grid, 128>>>(x, c, out, DIN, DOUT);

    const int total_v4 = (B * DOUT) / 4;
    epilogue_kernel<<<(total_v4 + 255) / 256, 256>>>(out, beta, DOUT / 4, total_v4);
}

// round 4
// speedup vs baseline: 1.0491x; 1.0491x over previous
#include <cuda_runtime.h>
#include <cstdint>

// sim[b,o] = sum_d |x[b,d] - c[o,d]|;  out[b,o] = beta[o] * (max(sim)*1.001 - sim[b,o])
// x[1024,512] fp32, centers[512,512] fp32, beta[512] fp32 -> out fp32 [1024,512].
// Single fused kernel: distance GEMM-like compute (packed f32x2), spin grid barrier
// for the global max, epilogue applied from registers. No intermediate gmem traffic.

#define BM 32
#define BN 64
#define KC 16          // K elements per chunk
#define KP (KC / 2)    // K float2-pairs per chunk
#define W_DIST 1.001f

__device__ int      g_max_bits = 0;   // bit pattern of global max (sims > 0 so int order == float order)
__device__ unsigned g_count1   = 0;   // barrier arrivals
__device__ unsigned g_count2   = 0;   // epilogue-done arrivals (guards the reset)

__device__ __forceinline__ unsigned long long addx2(unsigned long long a, unsigned long long b) {
    unsigned long long r;
    asm("add.rn.f32x2 %0, %1, %2;" : "=l"(r) : "l"(a), "l"(b));
    return r;
}

__global__ __launch_bounds__(128, 2) void rbf_fused_kernel(
    const float* __restrict__ x,       // [B, DIN]
    const float* __restrict__ c,       // [DOUT, DIN]
    const float* __restrict__ beta,    // [DOUT]
    float* __restrict__ out,           // [B, DOUT]
    int DIN, int DOUT, unsigned NB)
{
    // double-buffered k-pair-major tiles: [buf][pair][row]
    __shared__ float2 xs[2][KP][BM];   // 4 KB
    __shared__ float2 cs[2][KP][BN];   // 8 KB (negated centers)
    __shared__ float  wmax[4];
    __shared__ float  s_gm;

    const int tid = threadIdx.x;
    const int bm = blockIdx.y;
    const int bn = blockIdx.x;
    const int tr = tid >> 4;           // 0..7   -> m = tr + 8*i
    const int tc = tid & 15;           // 0..15  -> n = tc + 16*j

    unsigned long long acc[4][4];
#pragma unroll
    for (int i = 0; i < 4; i++)
#pragma unroll
        for (int j = 0; j < 4; j++) acc[i][j] = 0ULL;

    // coalesced float4 global-load mapping
    const int rl = tid >> 2;           // 0..31
    const int q  = tid & 3;            // 0..3
    const float4* xg  = reinterpret_cast<const float4*>(x + (size_t)(bm * BM + rl) * DIN) + q;
    const float4* cg0 = reinterpret_cast<const float4*>(c + (size_t)(bn * BN + rl)      * DIN) + q;
    const float4* cg1 = reinterpret_cast<const float4*>(c + (size_t)(bn * BN + rl + 32) * DIN) + q;

    float4 vx  = *xg;
    float4 vc0 = *cg0;
    float4 vc1 = *cg1;

    // prologue: fill buffer 0
    xs[0][q * 2 + 0][rl]      = make_float2(vx.x,  vx.y);
    xs[0][q * 2 + 1][rl]      = make_float2(vx.z,  vx.w);
    cs[0][q * 2 + 0][rl]      = make_float2(-vc0.x, -vc0.y);
    cs[0][q * 2 + 1][rl]      = make_float2(-vc0.z, -vc0.w);
    cs[0][q * 2 + 0][rl + 32] = make_float2(-vc1.x, -vc1.y);
    cs[0][q * 2 + 1][rl + 32] = make_float2(-vc1.z, -vc1.w);
    __syncthreads();

    const int nchunks = DIN / KC;
    for (int ch = 0; ch < nchunks; ch++) {
        const int pb = ch & 1;
        // prefetch next chunk (LDG latency overlaps compute)
        if (ch + 1 < nchunks) {
            vx  = xg [(ch + 1) * (KC / 4)];
            vc0 = cg0[(ch + 1) * (KC / 4)];
            vc1 = cg1[(ch + 1) * (KC / 4)];
        }

#pragma unroll
        for (int p = 0; p < KP; p++) {
            unsigned long long a[4], b[4];
#pragma unroll
            for (int i = 0; i < 4; i++)
                a[i] = *reinterpret_cast<const unsigned long long*>(&xs[pb][p][tr + 8 * i]);
#pragma unroll
            for (int j = 0; j < 4; j++)
                b[j] = *reinterpret_cast<const unsigned long long*>(&cs[pb][p][tc + 16 * j]);
#pragma unroll
            for (int i = 0; i < 4; i++)
#pragma unroll
                for (int j = 0; j < 4; j++) {
                    unsigned long long d = addx2(a[i], b[j]);     // x - c, packed
                    d &= 0x7FFFFFFF7FFFFFFFULL;                   // |.| both halves (alu pipe)
                    acc[i][j] = addx2(acc[i][j], d);              // packed accumulate
                }
        }

        // store prefetched chunk into the other buffer (prev reads of it were
        // protected by the previous iteration's barrier)
        if (ch + 1 < nchunks) {
            const int nb = 1 - pb;
            xs[nb][q * 2 + 0][rl]      = make_float2(vx.x,  vx.y);
            xs[nb][q * 2 + 1][rl]      = make_float2(vx.z,  vx.w);
            cs[nb][q * 2 + 0][rl]      = make_float2(-vc0.x, -vc0.y);
            cs[nb][q * 2 + 1][rl]      = make_float2(-vc0.z, -vc0.w);
            cs[nb][q * 2 + 0][rl + 32] = make_float2(-vc1.x, -vc1.y);
            cs[nb][q * 2 + 1][rl + 32] = make_float2(-vc1.z, -vc1.w);
        }
        __syncthreads();
    }

    // ---- per-thread sim fragment + block max ----
    float s[4][4];
    float tmax = 0.0f;
#pragma unroll
    for (int i = 0; i < 4; i++)
#pragma unroll
        for (int j = 0; j < 4; j++) {
            float2 v = *reinterpret_cast<float2*>(&acc[i][j]);
            s[i][j] = v.x + v.y;
            tmax = fmaxf(tmax, s[i][j]);
        }
#pragma unroll
    for (int off = 16; off > 0; off >>= 1)
        tmax = fmaxf(tmax, __shfl_xor_sync(0xffffffffu, tmax, off));
    if ((tid & 31) == 0) wmax[tid >> 5] = tmax;
    __syncthreads();

    // ---- grid barrier (all 256 CTAs are co-resident: launch_bounds(128,2), 256 <= 2*148) ----
    if (tid == 0) {
        float bmx = fmaxf(fmaxf(wmax[0], wmax[1]), fmaxf(wmax[2], wmax[3]));
        atomicMax(&g_max_bits, __float_as_int(bmx));
        __threadfence();                       // max visible before arrival
        atomicAdd(&g_count1, 1u);
        while (*((volatile unsigned*)&g_count1) < NB) { __nanosleep(64); }
        __threadfence();                       // acquire
        s_gm = __int_as_float(*((volatile int*)&g_max_bits)) * W_DIST;
        // signal "I read the max"; last arriver resets all state for the next graph replay
        unsigned old = atomicAdd(&g_count2, 1u);
        if (old == NB - 1u) {
            g_max_bits = 0;
            g_count1   = 0;
            g_count2   = 0;
        }
    }
    __syncthreads();
    const float gm = s_gm;

    // ---- epilogue from registers ----
    float bet[4];
#pragma unroll
    for (int j = 0; j < 4; j++) bet[j] = beta[bn * BN + tc + 16 * j];

#pragma unroll
    for (int i = 0; i < 4; i++) {
        const int row = bm * BM + tr + 8 * i;
        float* orow = out + (size_t)row * DOUT + bn * BN;
#pragma unroll
        for (int j = 0; j < 4; j++)
            orow[tc + 16 * j] = bet[j] * (gm - s[i][j]);
    }
}

extern "C" void kernel_launch(void* const* d_in, const int* in_sizes, int n_in,
                              void* d_out, int out_size)
{
    const float* x    = (const float*)d_in[0];
    const float* c    = (const float*)d_in[1];
    const float* beta = (const float*)d_in[2];
    float* out = (float*)d_out;

    const int DOUT = in_sizes[2];
    const int DIN  = in_sizes[1] / DOUT;
    const int B    = in_sizes[0] / DIN;

    dim3 grid(DOUT / BN, B / BM);
    const unsigned NB = grid.x * grid.y;
    rbf_fused_kernel<<<grid, 128>>>(x, c, beta, out, DIN, DOUT, NB);
}